// round 1
// baseline (speedup 1.0000x reference)
#include <cuda_runtime.h>

#define BLK      128
#define NF       32
#define NDOF     29
#define TSTRIDE  20                      // floats per staged pose (16 + 4 pad, 16B aligned, bank-safe)
#define CHUNK    2                       // frames per flush
#define FSTRIDE  (BLK * TSTRIDE + 16)    // 2576 floats per frame slab (+16 => 16-bank rotation)

// ---------------------------------------------------------------------------
// Fast sincos: Cody-Waite range reduction + degree-7/8 minimax-ish polys.
// All FMA-pipe; no MUFU. Accurate to ~4e-6 abs on |a| < ~100 (inputs ~N(0,1)).
// ---------------------------------------------------------------------------
__device__ __forceinline__ void fast_sincos(float a, float &s, float &c) {
    float q  = rintf(a * 0.63661977236758134f);   // a * 2/pi
    int   iq = (int)q;
    float r  = fmaf(q, -1.5707962513e+0f, a);     // pi/2 split hi
    r        = fmaf(q, -7.5497894159e-8f, r);     // pi/2 split lo
    float r2 = r * r;

    float ps = fmaf(r2, -1.9841270e-4f, 8.3333333e-3f);
    ps       = fmaf(r2, ps, -1.6666667e-1f);
    float sr = fmaf(r * r2, ps, r);               // sin(r)

    float pc = fmaf(r2, -1.3888889e-3f, 4.1666668e-2f);
    pc       = fmaf(r2, pc, -5.0e-1f);
    float cr = fmaf(r2, pc, 1.0f);                // cos(r)

    bool  sw = (iq & 1);
    float ss = sw ? cr : sr;
    float cc = sw ? sr : cr;
    unsigned sgn_s = ((unsigned)(iq & 2)) << 30;
    unsigned sgn_c = ((unsigned)((iq + 1) & 2)) << 30;
    s = __uint_as_float(__float_as_uint(ss) ^ sgn_s);
    c = __uint_as_float(__float_as_uint(cc) ^ sgn_c);
}

__global__ void __launch_bounds__(BLK, 4)
fk_kernel(const float* __restrict__ ja,        // [B, 29]
          const float* __restrict__ axes,      // [32, 3]  (unit)
          const float* __restrict__ origins,   // [32, 4, 4]
          const float* __restrict__ mmult,     // [2]
          const float* __restrict__ moff,      // [2]
          const int*   __restrict__ ctrl,      // [29]
          const int*   __restrict__ msrc,      // [2]
          const int*   __restrict__ mdst,      // [2]
          const int*   __restrict__ types,     // [32]
          float*       __restrict__ out,       // [B, 32, 4, 4]
          int Bn)
{
    __shared__ float s_orig[NF][12];      // top 3 rows of each origin
    __shared__ float s_axis[NF][3];
    __shared__ int   s_type[NF];
    __shared__ int   s_slot[NF];          // ctrl slot for this frame, or -1
    __shared__ int   s_mslot[NF];         // mimic source ctrl slot, or -1
    __shared__ float s_mc[NF][2];         // mimic mult, offset
    __shared__ float s_ang[BLK * 31];     // stride 31 => conflict-free per-thread rows
    __shared__ __align__(16) float s_out[CHUNK * FSTRIDE];

    const int tid = threadIdx.x;
    const int b0  = blockIdx.x * BLK;

    // ---- per-frame descriptor setup (uniform data, tiny) ----
    if (tid < NF) {
        const int f = tid;
        #pragma unroll
        for (int j = 0; j < 12; ++j) s_orig[f][j] = origins[f * 16 + j];
        s_axis[f][0] = axes[f * 3 + 0];
        s_axis[f][1] = axes[f * 3 + 1];
        s_axis[f][2] = axes[f * 3 + 2];
        s_type[f] = types[f];
        int slot = -1;
        for (int j = 0; j < NDOF; ++j) if (ctrl[j] == f) slot = j;
        s_slot[f] = slot;
        int ms = -1; float mm = 0.f, mo = 0.f;
        for (int m = 0; m < 2; ++m) {
            if (mdst[m] == f) {
                const int sf = msrc[m];
                for (int j = 0; j < NDOF; ++j) if (ctrl[j] == sf) ms = j;
                mm = mmult[m]; mo = moff[m];
            }
        }
        s_mslot[f] = ms; s_mc[f][0] = mm; s_mc[f][1] = mo;
    }

    // ---- stage this block's joint angles (coalesced global reads) ----
    for (int i = tid; i < BLK * NDOF; i += BLK) {
        const int bt = i / NDOF;
        const int j  = i - bt * NDOF;
        if (b0 + bt < Bn) s_ang[bt * 31 + j] = ja[(size_t)(b0 + bt) * NDOF + j];
    }
    __syncthreads();

    float P[12];     // running pose (3x4 affine)
    float S10[12];   // pose of frame 10 (branch point for frames 30, 31)

    float4* const out4 = reinterpret_cast<float4*>(out);

    #pragma unroll
    for (int f = 0; f < NF; ++f) {
        // -- joint angle for this frame --
        const int slot = s_slot[f];
        float a;
        if (slot >= 0) {
            a = s_ang[tid * 31 + slot];
        } else {
            const int ms = s_mslot[f];
            a = (ms >= 0) ? fmaf(s_ang[tid * 31 + ms], s_mc[f][0], s_mc[f][1]) : 0.f;
        }

        // -- rotation / translation of the joint motion --
        const int ty = s_type[f];
        float sn, cs;
        if (ty == 1) { fast_sincos(a, sn, cs); } else { sn = 0.f; cs = 1.f; }
        const float kx = s_axis[f][0], ky = s_axis[f][1], kz = s_axis[f][2];
        const float C = 1.0f - cs;
        // R = cs*I + sn*K + C*kk^T  (unit axis => theta == |a|, k == sign(a)*axis)
        const float R00 = fmaf(C, kx * kx, cs);
        const float R01 = fmaf(C, kx * ky, -sn * kz);
        const float R02 = fmaf(C, kx * kz,  sn * ky);
        const float R10 = fmaf(C, ky * kx,  sn * kz);
        const float R11 = fmaf(C, ky * ky, cs);
        const float R12 = fmaf(C, ky * kz, -sn * kx);
        const float R20 = fmaf(C, kz * kx, -sn * ky);
        const float R21 = fmaf(C, kz * ky,  sn * kx);
        const float R22 = fmaf(C, kz * kz, cs);
        const float tv = (ty == 2) ? a : 0.f;
        const float t0 = kx * tv, t1 = ky * tv, t2 = kz * tv;

        // -- local = origin[f] @ [R|t; 0 0 0 1] --
        float L[12];
        #pragma unroll
        for (int r = 0; r < 3; ++r) {
            const float O0 = s_orig[f][r * 4 + 0];
            const float O1 = s_orig[f][r * 4 + 1];
            const float O2 = s_orig[f][r * 4 + 2];
            const float O3 = s_orig[f][r * 4 + 3];
            L[r * 4 + 0] = fmaf(O0, R00, fmaf(O1, R10, O2 * R20));
            L[r * 4 + 1] = fmaf(O0, R01, fmaf(O1, R11, O2 * R21));
            L[r * 4 + 2] = fmaf(O0, R02, fmaf(O1, R12, O2 * R22));
            L[r * 4 + 3] = fmaf(O0, t0, fmaf(O1, t1, fmaf(O2, t2, O3)));
        }

        // -- chain: pose = parent_pose @ local --
        if (f == 0) {
            #pragma unroll
            for (int j = 0; j < 12; ++j) P[j] = L[j];
        } else {
            const float* PP = (f >= 30) ? S10 : P;
            float N[12];
            #pragma unroll
            for (int r = 0; r < 3; ++r) {
                const float p0 = PP[r * 4 + 0], p1 = PP[r * 4 + 1];
                const float p2 = PP[r * 4 + 2], p3 = PP[r * 4 + 3];
                #pragma unroll
                for (int cc2 = 0; cc2 < 4; ++cc2) {
                    float v = p0 * L[0 * 4 + cc2];
                    v = fmaf(p1, L[1 * 4 + cc2], v);
                    v = fmaf(p2, L[2 * 4 + cc2], v);
                    if (cc2 == 3) v += p3;
                    N[r * 4 + cc2] = v;
                }
            }
            #pragma unroll
            for (int j = 0; j < 12; ++j) P[j] = N[j];
        }
        if (f == 10) {
            #pragma unroll
            for (int j = 0; j < 12; ++j) S10[j] = P[j];
        }

        // -- stage pose into shared (bank-conflict-free: stride 20 floats) --
        {
            float4* so4 = reinterpret_cast<float4*>(
                s_out + (f & (CHUNK - 1)) * FSTRIDE + tid * TSTRIDE);
            so4[0] = make_float4(P[0], P[1], P[2],  P[3]);
            so4[1] = make_float4(P[4], P[5], P[6],  P[7]);
            so4[2] = make_float4(P[8], P[9], P[10], P[11]);
            so4[3] = make_float4(0.f, 0.f, 0.f, 1.f);
        }

        // -- flush CHUNK frames with fully-coalesced float4 stores --
        if ((f & (CHUNK - 1)) == (CHUNK - 1)) {
            __syncthreads();
            const int fbase = f - (CHUNK - 1);
            #pragma unroll
            for (int it = 0; it < (CHUNK * BLK * 4) / BLK; ++it) {
                const int v  = it * BLK + tid;
                const int q  = v & 3;
                const int fc = (v >> 2) & (CHUNK - 1);
                const int bt = v >> 3;
                if (b0 + bt < Bn) {
                    const float4 val = *reinterpret_cast<const float4*>(
                        s_out + fc * FSTRIDE + bt * TSTRIDE + q * 4);
                    out4[((size_t)(b0 + bt) * NF + (fbase + fc)) * 4 + q] = val;
                }
            }
            __syncthreads();
        }
    }
}

extern "C" void kernel_launch(void* const* d_in, const int* in_sizes, int n_in,
                              void* d_out, int out_size) {
    const float* ja      = (const float*)d_in[0];
    const float* axes    = (const float*)d_in[1];
    const float* origins = (const float*)d_in[2];
    const float* mm      = (const float*)d_in[3];
    const float* mo      = (const float*)d_in[4];
    const int*   ctrl    = (const int*)d_in[5];
    const int*   msrc    = (const int*)d_in[6];
    const int*   mdst    = (const int*)d_in[7];
    const int*   types   = (const int*)d_in[8];
    float*       out     = (float*)d_out;

    const int Bn   = in_sizes[0] / NDOF;
    const int grid = (Bn + BLK - 1) / BLK;
    fk_kernel<<<grid, BLK>>>(ja, axes, origins, mm, mo, ctrl, msrc, mdst, types, out, Bn);
}